// round 8
// baseline (speedup 1.0000x reference)
#include <cuda_runtime.h>
#include <cuda_bf16.h>
#include <cstdint>

// Problem: x [16, 256, 128, 128] f32.
//  1) weight[b,c] = mean over H,W
//  2) idx[b,:] = argsort(weight[b]) ascending, take first 16 (stable)
//  3) out[b,k,:,:] = x[b, idx[b,k], :, :]
//
// R8: ONE kernel, ONE graph node (no memset — sync state self-resets).
// Grid = 16 groups of 320 blocks: [256 mean blocks of batch b | 64 gather
// blocks of batch b]. In-order CTA delivery puts each batch's gather blocks
// resident right after that batch's mean blocks, so their spin is ~zero and
// their copy traffic overlaps the NEXT batches' mean reads. Only batch 15's
// 2 MiB gather is an unoverlapped tail.
// Select runs once per batch in the last-finisher mean block (atomic
// ticket), which also resets the mean counter. The 64th gather block of a
// batch resets the ready flag. All state returns to 0 => replay-safe.

#define B 16
#define C 256
#define HW 16384          // 128*128
#define K 16
#define GPB 320           // blocks per batch group: 256 mean + 64 gather

__device__ float g_weight[B * C];
__device__ int   g_idx[B * K];
__device__ int   g_count[B];       // mean completion tickets   (self-reset)
__device__ int   g_ready[B];       // select published flag     (self-reset)
__device__ int   g_gdone[B];       // gather completion tickets (self-reset)

__global__ __launch_bounds__(256, 8) void fused_kernel(const float* __restrict__ x,
                                                       float* __restrict__ out) {
    const int bid   = blockIdx.x;
    const int group = bid / GPB;                       // batch b
    const int r     = bid - group * GPB;               // 0..319
    const int t     = threadIdx.x;
    const int b     = group;

    if (r < C) {
        // ================= Phase A: mean of plane (b, r) =================
        const int bc = b * C + r;
        const float4* __restrict__ p =
            reinterpret_cast<const float4*>(x + (size_t)bc * HW);
        float s0 = 0.f, s1 = 0.f, s2 = 0.f, s3 = 0.f;
#pragma unroll
        for (int i = 0; i < 16; i += 4) {
            float4 v0 = __ldg(&p[t + (i + 0) * 256]);
            float4 v1 = __ldg(&p[t + (i + 1) * 256]);
            float4 v2 = __ldg(&p[t + (i + 2) * 256]);
            float4 v3 = __ldg(&p[t + (i + 3) * 256]);
            s0 += (v0.x + v0.y) + (v0.z + v0.w);
            s1 += (v1.x + v1.y) + (v1.z + v1.w);
            s2 += (v2.x + v2.y) + (v2.z + v2.w);
            s3 += (v3.x + v3.y) + (v3.z + v3.w);
        }
        float s = (s0 + s1) + (s2 + s3);
#pragma unroll
        for (int off = 16; off > 0; off >>= 1)
            s += __shfl_down_sync(0xFFFFFFFFu, s, off);

        __shared__ float sred[8];
        __shared__ int   s_last;
        if ((t & 31) == 0) sred[t >> 5] = s;
        __syncthreads();
        if (t < 8) {
            float v = sred[t];
#pragma unroll
            for (int off = 4; off > 0; off >>= 1)
                v += __shfl_down_sync(0xFFu, v, off);
            if (t == 0) {
                g_weight[bc] = v * (1.0f / (float)HW);
                __threadfence();                       // publish mean
                const int old = atomicAdd(&g_count[b], 1);
                s_last = (old == C - 1);               // last finisher
            }
        }
        __syncthreads();
        if (!s_last) return;

        // ---- last mean block of batch b: stable bottom-16 select ----
        __threadfence();
        __shared__ float sw[C];
        sw[t] = __ldcg(&g_weight[b * C + t]);
        __syncthreads();

        const float v = sw[t];
        int rank = 0;
#pragma unroll 8
        for (int j = 0; j < C; ++j) {
            const float u = sw[j];
            rank += (u < v) || (u == v && j < t);
        }
        if (rank < K) g_idx[b * K + rank] = t;
        __syncthreads();
        if (t == 0) {
            atomicExch(&g_count[b], 0);                // self-reset for replay
            __threadfence();                           // publish g_idx
            atomicExch(&g_ready[b], 1);                // ready flag
        }
        return;
    }

    // ================= Phase B: gather (64 blocks per batch) =================
    const int kk    = r - C;                           // 0..63
    const int k     = kk >> 2;                         // output rank 0..15
    const int q     = kk & 3;                          // quarter of plane
    const int plane = b * K + k;

    if (t == 0) {
        while (atomicAdd(&g_ready[b], 0) == 0) __nanosleep(64);
    }
    __syncthreads();                                   // acquire for block

    const int c = __ldcg(&g_idx[plane]);

    const float4* __restrict__ src = reinterpret_cast<const float4*>(
        x + ((size_t)b * C + c) * HW) + q * 1024;
    float4* __restrict__ dst = reinterpret_cast<float4*>(
        out + (size_t)plane * HW) + q * 1024;

    float4 w[4];
#pragma unroll
    for (int i = 0; i < 4; ++i)
        w[i] = __ldg(&src[t + i * 256]);               // 4 loads in flight
#pragma unroll
    for (int i = 0; i < 4; ++i)
        __stcs(&dst[t + i * 256], w[i]);               // streaming stores

    __syncthreads();                                   // copy done block-wide
    if (t == 0) {
        const int old = atomicAdd(&g_gdone[b], 1);
        if (old == 63) {                               // last gather of batch
            atomicExch(&g_gdone[b], 0);                // self-reset
            atomicExch(&g_ready[b], 0);                // self-reset
        }
    }
}

// ---------------------------------------------------------------------------
extern "C" void kernel_launch(void* const* d_in, const int* in_sizes, int n_in,
                              void* d_out, int out_size) {
    const float* x = (const float*)d_in[0];
    float* out = (float*)d_out;

    fused_kernel<<<B * GPB, 256>>>(x, out);
}

// round 9
// speedup vs baseline: 1.0045x; 1.0045x over previous
#include <cuda_runtime.h>
#include <cuda_bf16.h>
#include <cstdint>

// Problem: x [16, 256, 128, 128] f32.
//  1) weight[b,c] = mean over H,W
//  2) idx[b,:] = argsort(weight[b]) ascending, take first 16 (stable)
//  3) out[b,k,:,:] = x[b, idx[b,k], :, :]
//
// R9: ONE kernel, ONE graph node (self-resetting sync, no memset).
// Grid order (5120 blocks, in-order CTA delivery):
//   [0,1440)        : means 0..1439            (batches 0..5.6)
//   [1440,4640)     : 10 chunks of 320 = [64 gathers of batch i | 256 means]
//   [4640,4736)     : means 4000..4095
//   [4736,5120)     : tail gathers, batches 10..15
// Gathers of batch i sit >= one full wave (~1184 blocks) after batch i's
// means, so they arrive with their data already published (near-zero spin)
// and their copy overlaps later batches' mean reads. R8's failure (spin in
// the same wave as own-batch means) is avoided by construction; R7's
// failure (all gathers serialized in the final wave) only affects the last
// few batches.

#define B 16
#define C 256
#define HW 16384          // 128*128
#define K 16

__device__ float g_weight[B * C];
__device__ int   g_idx[B * K];
__device__ int   g_count[B];       // mean tickets   (self-reset by select)
__device__ int   g_ready[B];       // select done    (self-reset by last gather)
__device__ int   g_gdone[B];       // gather tickets (self-reset by last gather)

__global__ __launch_bounds__(256, 8) void fused_kernel(const float* __restrict__ x,
                                                       float* __restrict__ out) {
    const int bid = blockIdx.x;
    const int t   = threadIdx.x;

    // ---- decode grid position -> (mean plane m) or (gather batch b, kk) ----
    int m = -1, gb = 0, kk = 0;
    if (bid < 1440) {
        m = bid;
    } else if (bid < 4640) {
        const int r = bid - 1440;
        const int chunk = r / 320;
        const int off   = r - chunk * 320;
        if (off < 64) { gb = chunk; kk = off; }
        else          { m = 1440 + chunk * 256 + (off - 64); }
    } else if (bid < 4736) {
        m = 4000 + (bid - 4640);
    } else {
        const int r = bid - 4736;
        gb = 10 + (r >> 6);
        kk = r & 63;
    }

    if (m >= 0) {
        // ================= Phase A: mean of plane m =================
        const int b = m >> 8;
        const float4* __restrict__ p =
            reinterpret_cast<const float4*>(x + (size_t)m * HW);
        float s0 = 0.f, s1 = 0.f, s2 = 0.f, s3 = 0.f;
#pragma unroll
        for (int i = 0; i < 16; i += 4) {
            float4 v0 = __ldg(&p[t + (i + 0) * 256]);
            float4 v1 = __ldg(&p[t + (i + 1) * 256]);
            float4 v2 = __ldg(&p[t + (i + 2) * 256]);
            float4 v3 = __ldg(&p[t + (i + 3) * 256]);
            s0 += (v0.x + v0.y) + (v0.z + v0.w);
            s1 += (v1.x + v1.y) + (v1.z + v1.w);
            s2 += (v2.x + v2.y) + (v2.z + v2.w);
            s3 += (v3.x + v3.y) + (v3.z + v3.w);
        }
        float s = (s0 + s1) + (s2 + s3);
#pragma unroll
        for (int off = 16; off > 0; off >>= 1)
            s += __shfl_down_sync(0xFFFFFFFFu, s, off);

        __shared__ float sred[8];
        __shared__ int   s_last;
        if ((t & 31) == 0) sred[t >> 5] = s;
        __syncthreads();
        if (t < 8) {
            float v = sred[t];
#pragma unroll
            for (int off = 4; off > 0; off >>= 1)
                v += __shfl_down_sync(0xFFu, v, off);
            if (t == 0) {
                g_weight[m] = v * (1.0f / (float)HW);
                __threadfence();                       // publish mean
                const int old = atomicAdd(&g_count[b], 1);
                s_last = (old == C - 1);               // last finisher
            }
        }
        __syncthreads();
        if (!s_last) return;

        // ---- last mean block of batch b: stable bottom-16 select ----
        __threadfence();
        __shared__ float sw[C];
        sw[t] = __ldcg(&g_weight[b * C + t]);
        __syncthreads();

        const float v = sw[t];
        int rank = 0;
#pragma unroll 8
        for (int j = 0; j < C; ++j) {
            const float u = sw[j];
            rank += (u < v) || (u == v && j < t);
        }
        if (rank < K) g_idx[b * K + rank] = t;
        __syncthreads();
        if (t == 0) {
            atomicExch(&g_count[b], 0);                // self-reset for replay
            __threadfence();                           // publish g_idx
            atomicExch(&g_ready[b], 1);                // ready flag
        }
        return;
    }

    // ================= Phase B: gather (64 blocks per batch) =================
    const int b     = gb;
    const int k     = kk >> 2;                         // output rank 0..15
    const int q     = kk & 3;                          // quarter of plane
    const int plane = b * K + k;

    if (t == 0) {
        while (atomicAdd(&g_ready[b], 0) == 0) __nanosleep(256);
    }
    __syncthreads();                                   // acquire for block

    const int c = __ldcg(&g_idx[plane]);

    const float4* __restrict__ src = reinterpret_cast<const float4*>(
        x + ((size_t)b * C + c) * HW) + q * 1024;
    float4* __restrict__ dst = reinterpret_cast<float4*>(
        out + (size_t)plane * HW) + q * 1024;

    float4 w[4];
#pragma unroll
    for (int i = 0; i < 4; ++i)
        w[i] = __ldg(&src[t + i * 256]);               // 4 loads in flight
#pragma unroll
    for (int i = 0; i < 4; ++i)
        __stcs(&dst[t + i * 256], w[i]);               // streaming stores

    __syncthreads();                                   // copy done block-wide
    if (t == 0) {
        const int old = atomicAdd(&g_gdone[b], 1);
        if (old == 63) {                               // last gather of batch
            atomicExch(&g_gdone[b], 0);                // self-reset
            atomicExch(&g_ready[b], 0);                // self-reset
        }
    }
}

// ---------------------------------------------------------------------------
extern "C" void kernel_launch(void* const* d_in, const int* in_sizes, int n_in,
                              void* d_out, int out_size) {
    const float* x = (const float*)d_in[0];
    float* out = (float*)d_out;

    fused_kernel<<<5120, 256>>>(x, out);
}

// round 10
// speedup vs baseline: 1.0393x; 1.0347x over previous
#include <cuda_runtime.h>
#include <cuda_bf16.h>
#include <cstdint>

// Problem: x [16, 256, 128, 128] f32.
//  1) weight[b,c] = mean over H,W
//  2) idx[b,:] = argsort(weight[b]) ascending, take first 16 (stable)
//  3) out[b,k,:,:] = x[b, idx[b,k], :, :]
//
// R10 = measured-best combination:
//  - R7 layout: 4096 mean blocks first, ALL gather blocks strictly after.
//    Mean pass runs at its standalone 80%-of-peak form; gather blocks are
//    only delivered as mean blocks retire, so their data is already
//    published (spin ~ 0, except a bounded sliver for the last batch).
//  - R8 self-resetting sync: ONE graph node, no memset (saves ~3us gaps).
//  - Gather split into 2048 eighth-plane blocks (8KB each): they trickle
//    into SM slots freed one-by-one during the final mean wave's drain,
//    overlapping part of the tail, and shrink the drain ramp that capped
//    the coarse gather at ~8.3us. __stcs stores keep input L2-resident.

#define B 16
#define C 256
#define HW 16384          // 128*128
#define K 16
#define MEAN_BLOCKS 4096
#define GATHER_BLOCKS 2048   // 8 per output plane (eighth planes)

__device__ float g_weight[B * C];
__device__ int   g_idx[B * K];
__device__ int   g_count[B];      // mean tickets   (self-reset by select)
__device__ int   g_ready[B];      // select done    (self-reset by last gather)
__device__ int   g_gdone[B];      // gather tickets (self-reset by last gather)

__global__ __launch_bounds__(256, 8) void fused_kernel(const float* __restrict__ x,
                                                       float* __restrict__ out) {
    const int bid = blockIdx.x;
    const int t   = threadIdx.x;

    if (bid < MEAN_BLOCKS) {
        // ================= Phase A: mean of plane bid =================
        const int b = bid >> 8;
        const float4* __restrict__ p =
            reinterpret_cast<const float4*>(x + (size_t)bid * HW);
        float s0 = 0.f, s1 = 0.f, s2 = 0.f, s3 = 0.f;
#pragma unroll
        for (int i = 0; i < 16; i += 4) {
            float4 v0 = __ldg(&p[t + (i + 0) * 256]);
            float4 v1 = __ldg(&p[t + (i + 1) * 256]);
            float4 v2 = __ldg(&p[t + (i + 2) * 256]);
            float4 v3 = __ldg(&p[t + (i + 3) * 256]);
            s0 += (v0.x + v0.y) + (v0.z + v0.w);
            s1 += (v1.x + v1.y) + (v1.z + v1.w);
            s2 += (v2.x + v2.y) + (v2.z + v2.w);
            s3 += (v3.x + v3.y) + (v3.z + v3.w);
        }
        float s = (s0 + s1) + (s2 + s3);
#pragma unroll
        for (int off = 16; off > 0; off >>= 1)
            s += __shfl_down_sync(0xFFFFFFFFu, s, off);

        __shared__ float sred[8];
        __shared__ int   s_last;
        if ((t & 31) == 0) sred[t >> 5] = s;
        __syncthreads();
        if (t < 8) {
            float v = sred[t];
#pragma unroll
            for (int off = 4; off > 0; off >>= 1)
                v += __shfl_down_sync(0xFFu, v, off);
            if (t == 0) {
                g_weight[bid] = v * (1.0f / (float)HW);
                __threadfence();                       // publish mean
                const int old = atomicAdd(&g_count[b], 1);
                s_last = (old == C - 1);               // last finisher
            }
        }
        __syncthreads();
        if (!s_last) return;

        // ---- last mean block of batch b: stable bottom-16 select ----
        __threadfence();
        __shared__ float sw[C];
        sw[t] = __ldcg(&g_weight[b * C + t]);
        __syncthreads();

        const float v = sw[t];
        int rank = 0;
#pragma unroll 8
        for (int j = 0; j < C; ++j) {
            const float u = sw[j];
            rank += (u < v) || (u == v && j < t);
        }
        if (rank < K) g_idx[b * K + rank] = t;
        __syncthreads();
        if (t == 0) {
            atomicExch(&g_count[b], 0);                // self-reset for replay
            __threadfence();                           // publish g_idx
            atomicExch(&g_ready[b], 1);                // ready flag
        }
        return;
    }

    // ============ Phase B: gather, 2048 eighth-plane blocks ============
    const int g     = bid - MEAN_BLOCKS;               // 0..2047
    const int plane = g >> 3;                          // 0..255
    const int q     = g & 7;                           // eighth of plane
    const int b     = plane >> 4;

    if (t == 0) {
        while (atomicAdd(&g_ready[b], 0) == 0) __nanosleep(64);
    }
    __syncthreads();                                   // acquire for block

    const int c = __ldcg(&g_idx[plane]);

    const float4* __restrict__ src = reinterpret_cast<const float4*>(
        x + ((size_t)b * C + c) * HW) + q * 512;
    float4* __restrict__ dst = reinterpret_cast<float4*>(
        out + (size_t)plane * HW) + q * 512;

    // 2 float4 per thread, loads batched before stores
    float4 w0 = __ldg(&src[t]);
    float4 w1 = __ldg(&src[t + 256]);
    __stcs(&dst[t],       w0);
    __stcs(&dst[t + 256], w1);

    __syncthreads();                                   // copy done block-wide
    if (t == 0) {
        const int old = atomicAdd(&g_gdone[b], 1);
        if (old == 127) {                              // last gather of batch
            atomicExch(&g_gdone[b], 0);                // self-reset
            atomicExch(&g_ready[b], 0);                // self-reset
        }
    }
}

// ---------------------------------------------------------------------------
extern "C" void kernel_launch(void* const* d_in, const int* in_sizes, int n_in,
                              void* d_out, int out_size) {
    const float* x = (const float*)d_in[0];
    float* out = (float*)d_out;

    fused_kernel<<<MEAN_BLOCKS + GATHER_BLOCKS, 256>>>(x, out);
}